// round 3
// baseline (speedup 1.0000x reference)
#include <cuda_runtime.h>
#include <cstdint>

#define Nn 8192
#define Mm 512
#define KK 512
#define TSTEPS 48

// ---------------- device scratch (static .bss; allocation-free) ----------------
__device__ float g_px[(size_t)(Nn + 1) * 2560];   // childsum x-proj; row Nn stays 0 (sentinel)
__device__ float g_qx[(size_t)Nn * 2560];         // chain x-proj
__device__ float g_acch[(size_t)(Nn + 1) * Mm];
__device__ float g_accfc[(size_t)(Nn + 1) * Mm];
__device__ float g_acczc[(size_t)(Nn + 1) * Mm];
__device__ float g_csc[(size_t)Nn * Mm];
__device__ float g_csh[(size_t)Nn * Mm];
__device__ float g_chc[(size_t)(Nn + 1) * Mm];    // row Nn stays 0 (root's phantom parent)
__device__ float g_chh[(size_t)(Nn + 1) * Mm];
__device__ float g_csio[(size_t)Nn * 1024];
__device__ float g_csw[(size_t)Nn * Mm];
__device__ float g_csfz[(size_t)Nn * 1024];
__device__ float g_chg[(size_t)Nn * 2048];
__device__ float g_chs[(size_t)Nn * Mm];
__device__ float g_chig[(size_t)Nn * Mm];
__device__ float g_chog[(size_t)Nn * Mm];
__device__ float g_chfc[(size_t)Nn * Mm];
__device__ float g_chw[(size_t)Nn * Mm];

__device__ int g_parent[Nn];
__device__ int g_depth[Nn];
__device__ int g_order[Nn];
__device__ int g_parorder[Nn];
__device__ int g_lvlstart[256];
__device__ int g_lvlcnt[256];
__device__ int g_maxdepth;

// ---------------- helpers ----------------
__device__ __forceinline__ float sigf(float x) { return 1.f / (1.f + __expf(-x)); }

__device__ __forceinline__ unsigned long long pack2(float x, float y) {
    unsigned long long r;
    asm("mov.b64 %0, {%1, %2};" : "=l"(r) : "f"(x), "f"(y));
    return r;
}
__device__ __forceinline__ void unpack2(unsigned long long v, float& x, float& y) {
    asm("mov.b64 {%0, %1}, %2;" : "=f"(x), "=f"(y) : "l"(v));
}
__device__ __forceinline__ void fma2(unsigned long long& d, unsigned long long a,
                                     unsigned long long b) {
    asm("fma.rn.f32x2 %0, %1, %2, %0;" : "+l"(d) : "l"(a), "l"(b));
}

__device__ __forceinline__ void atomicMaxF(float* addr, float val) {
    int* ia = (int*)addr;
    int old = *ia;
    while (__int_as_float(old) < val) {
        int assumed = old;
        old = atomicCAS(ia, assumed, __float_as_int(val));
        if (old == assumed) break;
    }
}

// ---------------- 64x64 fp32 GEMM tile, K=512, 256 threads, f32x2 FMA ----------
// out[orow(gr)][c] = sum_k A[arow(gr)][k] * W[c][k] + bias[c]
struct __align__(16) SmemT { float As[16][68]; float Ws[16][68]; };

__device__ void gemm_tile64(const float* __restrict__ A,
                            const int* __restrict__ arows,
                            const float* __restrict__ W,
                            const float* __restrict__ bias,
                            float* __restrict__ out,
                            const int* __restrict__ orows,
                            int ldo, int n, int rt, int ct, SmemT* sm) {
    const int tid = threadIdx.x;
    const int tx = tid & 15, ty = tid >> 4;
    const int lk = tid & 15, lr = tid >> 4;
    const int r0 = rt << 6, c0 = ct << 6;

    const float* aptr[4];
    bool rv[4];
#pragma unroll
    for (int m = 0; m < 4; m++) {
        int gr = r0 + lr + (m << 4);
        rv[m] = gr < n;
        int ar = rv[m] ? (arows ? arows[gr] : gr) : 0;
        aptr[m] = A + (size_t)ar * KK;
    }
    const float* wptr[4];
#pragma unroll
    for (int m = 0; m < 4; m++) wptr[m] = W + (size_t)(c0 + lr + (m << 4)) * KK;

    unsigned long long acc[4][2];
#pragma unroll
    for (int m = 0; m < 4; m++) { acc[m][0] = 0ull; acc[m][1] = 0ull; }

    for (int k0 = 0; k0 < KK; k0 += 16) {
#pragma unroll
        for (int m = 0; m < 4; m++) {
            sm->As[lk][lr + (m << 4)] = rv[m] ? aptr[m][k0 + lk] : 0.f;
            sm->Ws[lk][lr + (m << 4)] = wptr[m][k0 + lk];
        }
        __syncthreads();
#pragma unroll
        for (int k = 0; k < 16; k++) {
            ulonglong2 w2 = *(const ulonglong2*)&sm->Ws[k][tx << 2];
#pragma unroll
            for (int m = 0; m < 4; m++) {
                float a = sm->As[k][ty + (m << 4)];
                unsigned long long ap = pack2(a, a);
                fma2(acc[m][0], ap, w2.x);
                fma2(acc[m][1], ap, w2.y);
            }
        }
        __syncthreads();
    }
#pragma unroll
    for (int m = 0; m < 4; m++) {
        int gr = r0 + ty + (m << 4);
        if (gr < n) {
            int orow = orows ? orows[gr] : gr;
            float x0, x1, x2, x3;
            unpack2(acc[m][0], x0, x1);
            unpack2(acc[m][1], x2, x3);
            int c = c0 + (tx << 2);
            float4 v = make_float4(x0 + bias[c], x1 + bias[c + 1],
                                   x2 + bias[c + 2], x3 + bias[c + 3]);
            *(float4*)(out + (size_t)orow * ldo + c) = v;
        }
    }
}

// ---------------- setup kernels ----------------
__global__ __launch_bounds__(1024) void k_decode(const void* praw) {
    const int tid = threadIdx.x;
    __shared__ int s_is32;
    if (tid == 0) s_is32 = 0;
    __syncthreads();
    const int* w = (const int*)praw;
    for (int i = tid; i < Nn / 2; i += 1024)
        if (w[2 * i + 1] != 0) atomicOr(&s_is32, 1);
    __syncthreads();
    if (s_is32) {
        for (int i = tid; i < Nn; i += 1024) g_parent[i] = w[i];
    } else {
        const long long* l = (const long long*)praw;
        for (int i = tid; i < Nn; i += 1024) g_parent[i] = (int)l[i];
    }
}

__global__ void k_depth() {
    int idx = blockIdx.x * blockDim.x + threadIdx.x;
    int stride = gridDim.x * blockDim.x;
    for (int i = idx; i < Nn; i += stride) {
        int d = 0, j = i;
        while (j != 0) { j = g_parent[j]; d++; }
        g_depth[i] = d;
    }
}

__global__ __launch_bounds__(1024) void k_levels() {
    const int tid = threadIdx.x;
    __shared__ int s_maxd;
    if (tid == 0) s_maxd = 0;
    for (int d = tid; d < 256; d += 1024) g_lvlcnt[d] = 0;
    __syncthreads();
    int lm = 0;
    for (int i = tid; i < Nn; i += 1024) lm = max(lm, g_depth[i]);
    atomicMax(&s_maxd, lm);
    __syncthreads();
    if (tid == 0) g_maxdepth = s_maxd;
    for (int i = tid; i < Nn; i += 1024) atomicAdd(&g_lvlcnt[g_depth[i]], 1);
    __syncthreads();
    if (tid == 0) {
        int s = 0;
        for (int d = 0; d < 255; d++) { g_lvlstart[d] = s; s += g_lvlcnt[d]; }
        g_lvlstart[255] = s;
    }
    __syncthreads();
    for (int d = tid; d < 256; d += 1024) g_lvlcnt[d] = 0;
    __syncthreads();
    for (int i = tid; i < Nn; i += 1024) {
        int d = g_depth[i];
        int pos = atomicAdd(&g_lvlcnt[d], 1);
        g_order[g_lvlstart[d] + pos] = i;
    }
    __syncthreads();
    for (int p = tid; p < Nn; p += 1024) g_parorder[p] = g_parent[g_order[p]];
}

__global__ void k_zero(float* __restrict__ out) {
    size_t idx = (size_t)blockIdx.x * blockDim.x + threadIdx.x;
    size_t stride = (size_t)gridDim.x * blockDim.x;
    const size_t n1 = (size_t)(Nn + 1) * Mm;
    for (size_t i = idx; i < n1; i += stride) {
        g_acch[i] = 0.f; g_accfc[i] = 0.f; g_acczc[i] = 0.f;
        g_chc[i] = 0.f; g_chh[i] = 0.f;
    }
    for (size_t i = idx; i < 512; i += stride) out[512 + i] = -1e30f;
}

// ---------------- big input-projection GEMM (px and qx) ----------------
__global__ __launch_bounds__(256) void k_big(const float* __restrict__ x,
                                             const float* __restrict__ csWx,
                                             const float* __restrict__ csbx,
                                             const float* __restrict__ chWx,
                                             const float* __restrict__ chbx) {
    __shared__ SmemT sm;
    int rt = blockIdx.x;   // 0..127
    int ct = blockIdx.y;   // 0..79
    if (ct < 40)
        gemm_tile64(x, nullptr, csWx, csbx, g_px, nullptr, 2560, Nn, rt, ct, &sm);
    else
        gemm_tile64(x, nullptr, chWx, chbx, g_qx, nullptr, 2560, Nn, rt, ct - 40, &sm);
}

// ---------------- superstep kernels ----------------
__global__ __launch_bounds__(256) void k_stage1(int t,
        const float* __restrict__ chWh, const float* __restrict__ chbh,
        const float* __restrict__ csWio, const float* __restrict__ csbio,
        const float* __restrict__ csWum, const float* __restrict__ csbum) {
    __shared__ SmemT sm;
    const int maxd = g_maxdepth;
    const int ct = blockIdx.y;
    if (blockIdx.z == 0) {                        // chain: g = h_parent @ Wh^T + bh
        if (t > maxd) return;
        int s = g_lvlstart[t], n = g_lvlstart[t + 1] - s;
        for (int rt = blockIdx.x; rt * 64 < n; rt += gridDim.x)
            gemm_tile64(g_chh, g_parorder + s, chWh, chbh, g_chg, g_order + s,
                        2048, n, rt, ct, &sm);
    } else {                                      // childsum: io and w
        int d = maxd - t;
        if (d < 0 || ct >= 24) return;
        int s = g_lvlstart[d], n = g_lvlstart[d + 1] - s;
        for (int rt = blockIdx.x; rt * 64 < n; rt += gridDim.x) {
            if (ct < 16)
                gemm_tile64(g_acch, g_order + s, csWio, csbio, g_csio, g_order + s,
                            1024, n, rt, ct, &sm);
            else
                gemm_tile64(g_acczc, g_order + s, csWum, csbum, g_csw, g_order + s,
                            512, n, rt, ct - 16, &sm);
        }
    }
}

__global__ void k_e1(int t) {
    const int maxd = g_maxdepth;
    int cnt_ch = 0, cs0 = 0;
    if (t <= maxd) { cs0 = g_lvlstart[t]; cnt_ch = g_lvlstart[t + 1] - cs0; }
    int d = maxd - t, cnt_cs = 0, ds0 = 0;
    if (d >= 0) { ds0 = g_lvlstart[d]; cnt_cs = g_lvlstart[d + 1] - ds0; }
    int total = (cnt_ch + cnt_cs) * Mm;
    int idx = blockIdx.x * blockDim.x + threadIdx.x;
    int stride = gridDim.x * blockDim.x;
    for (int e = idx; e < total; e += stride) {
        if (e < cnt_ch * Mm) {
            int r = e >> 9, j = e & 511;
            int node = g_order[cs0 + r];
            int p = g_parent[node];
            const float* q = g_qx + (size_t)node * 2560;
            const float* g = g_chg + (size_t)node * 2048;
            float ig = sigf(q[j] + g[j]);
            float og = sigf(q[512 + j] + g[512 + j]);
            float fg = sigf(q[1024 + j] + g[1024 + j]);
            float zg = sigf(q[1536 + j] + g[1536 + j]);
            float pc = g_chc[(size_t)p * Mm + j];
            size_t nj = (size_t)node * Mm + j;
            g_chs[nj] = zg * tanhf(pc);
            g_chig[nj] = ig; g_chog[nj] = og; g_chfc[nj] = fg * pc;
        } else {
            int k = e - cnt_ch * Mm;
            int r = k >> 9, j = k & 511;
            int node = g_order[ds0 + r];
            const float* px = g_px + (size_t)node * 2560;
            const float* io = g_csio + (size_t)node * 1024;
            size_t nj = (size_t)node * Mm + j;
            float ig = sigf(px[j] + io[j]);
            float og = sigf(px[1024 + j] + io[512 + j]);
            float u = tanhf(px[2048 + j] + g_csw[nj]);
            float c = ig * u + g_accfc[nj];
            float h = og * tanhf(c);
            g_csc[nj] = c; g_csh[nj] = h;
        }
    }
}

__global__ __launch_bounds__(256) void k_stage2(int t,
        const float* __restrict__ chWum, const float* __restrict__ chbum,
        const float* __restrict__ csWfz, const float* __restrict__ csbfz) {
    __shared__ SmemT sm;
    const int maxd = g_maxdepth;
    const int ct = blockIdx.y;
    if (blockIdx.z == 0) {                        // chain: w = s @ Wum^T
        if (t > maxd || ct >= 8) return;
        int s = g_lvlstart[t], n = g_lvlstart[t + 1] - s;
        for (int rt = blockIdx.x; rt * 64 < n; rt += gridDim.x)
            gemm_tile64(g_chs, g_order + s, chWum, chbum, g_chw, g_order + s,
                        512, n, rt, ct, &sm);
    } else {                                      // childsum: fz = h @ Wfz^T
        int d = maxd - t;
        if (d < 0) return;
        int s = g_lvlstart[d], n = g_lvlstart[d + 1] - s;
        for (int rt = blockIdx.x; rt * 64 < n; rt += gridDim.x)
            gemm_tile64(g_csh, g_order + s, csWfz, csbfz, g_csfz, g_order + s,
                        1024, n, rt, ct, &sm);
    }
}

__global__ void k_e2(int t) {
    const int maxd = g_maxdepth;
    int cnt_ch = 0, cs0 = 0;
    if (t <= maxd) { cs0 = g_lvlstart[t]; cnt_ch = g_lvlstart[t + 1] - cs0; }
    int d = maxd - t, cnt_cs = 0, ds0 = 0;
    if (d >= 0) { ds0 = g_lvlstart[d]; cnt_cs = g_lvlstart[d + 1] - ds0; }
    int total = (cnt_ch + cnt_cs) * Mm;
    int idx = blockIdx.x * blockDim.x + threadIdx.x;
    int stride = gridDim.x * blockDim.x;
    for (int e = idx; e < total; e += stride) {
        if (e < cnt_ch * Mm) {
            int r = e >> 9, j = e & 511;
            int node = g_order[cs0 + r];
            size_t nj = (size_t)node * Mm + j;
            float u = tanhf(g_qx[(size_t)node * 2560 + 2048 + j] + g_chw[nj]);
            float c = g_chig[nj] * u + g_chfc[nj];
            float h = g_chog[nj] * tanhf(c);
            g_chc[nj] = c; g_chh[nj] = h;
        } else {
            int k = e - cnt_ch * Mm;
            int r = k >> 9, j = k & 511;
            int node = g_order[ds0 + r];
            int p = g_parent[node];
            size_t nj = (size_t)node * Mm + j;
            const float* fz = g_csfz + (size_t)node * 1024;
            float c = g_csc[nj], h = g_csh[nj];
            float f = sigf(g_px[(size_t)p * 2560 + 512 + j] + fz[j]);
            float z = sigf(g_px[(size_t)p * 2560 + 1536 + j] + fz[512 + j]);
            size_t pj = (size_t)p * Mm + j;
            atomicAdd(&g_acch[pj], h);
            atomicAdd(&g_accfc[pj], f * c);
            atomicAdd(&g_acczc[pj], z * tanhf(c));
        }
    }
}

// ---------------- final: frep = h_root (node 0), brep = colmax(chain h) --------
__global__ void k_final(float* __restrict__ out) {
    int j = threadIdx.x;
    if (blockIdx.x == 32) {
        out[j] = g_csh[j];   // root = node 0
        return;
    }
    int r0 = blockIdx.x * 256;
    float pm = -1e30f;
    for (int r = r0; r < r0 + 256; r++)
        pm = fmaxf(pm, g_chh[(size_t)r * Mm + j]);
    atomicMaxF(out + 512 + j, pm);
}

// ---------------- launch ----------------
extern "C" void kernel_launch(void* const* d_in, const int* in_sizes, int n_in,
                              void* d_out, int out_size) {
    const float* inputs = (const float*)d_in[0];
    const void* parent = d_in[1];
    const float* csWx = (const float*)d_in[2];
    const float* csbx = (const float*)d_in[3];
    const float* csWio = (const float*)d_in[4];
    const float* csbio = (const float*)d_in[5];
    const float* csWfz = (const float*)d_in[6];
    const float* csbfz = (const float*)d_in[7];
    const float* csWum = (const float*)d_in[8];
    const float* csbum = (const float*)d_in[9];
    const float* chWx = (const float*)d_in[10];
    const float* chbx = (const float*)d_in[11];
    const float* chWh = (const float*)d_in[12];
    const float* chbh = (const float*)d_in[13];
    const float* chWum = (const float*)d_in[14];
    const float* chbum = (const float*)d_in[15];
    float* out = (float*)d_out;

    k_decode<<<1, 1024>>>(parent);
    k_depth<<<64, 256>>>();
    k_levels<<<1, 1024>>>();
    k_zero<<<512, 256>>>(out);
    k_big<<<dim3(128, 80), 256>>>(inputs, csWx, csbx, chWx, chbx);
    for (int t = 0; t < TSTEPS; t++) {
        k_stage1<<<dim3(32, 32, 2), 256>>>(t, chWh, chbh, csWio, csbio, csWum, csbum);
        k_e1<<<512, 256>>>(t);
        k_stage2<<<dim3(32, 16, 2), 256>>>(t, chWum, chbum, csWfz, csbfz);
        k_e2<<<512, 256>>>(t);
    }
    k_final<<<33, 512>>>(out);
}

// round 6
// speedup vs baseline: 1.4503x; 1.4503x over previous
#include <cuda_runtime.h>
#include <cstdint>

#define Nn 8192
#define Mm 512
#define TSTEPS 44

// ---------------- device scratch (static .bss; allocation-free) ----------------
__device__ float g_px[(size_t)(Nn + 1) * 2560];   // childsum x-proj; row Nn stays 0 (sentinel)
__device__ float g_qx[(size_t)Nn * 2560];         // chain x-proj
__device__ float g_acch[(size_t)(Nn + 1) * Mm];
__device__ float g_accfc[(size_t)(Nn + 1) * Mm];
__device__ float g_acczc[(size_t)(Nn + 1) * Mm];
__device__ float g_csc[(size_t)Nn * Mm];
__device__ float g_csh[(size_t)Nn * Mm];
__device__ float g_chc[(size_t)(Nn + 1) * Mm];    // row Nn stays 0 forever (root's phantom)
__device__ float g_chh[(size_t)(Nn + 1) * Mm];    // row Nn stays 0 forever
__device__ float g_csio[(size_t)Nn * 1024];
__device__ float g_csw[(size_t)Nn * Mm];
__device__ float g_csfz[(size_t)Nn * 1024];
__device__ float g_chg[(size_t)Nn * 2048];
__device__ float g_chs[(size_t)Nn * Mm];
__device__ float g_chig[(size_t)Nn * Mm];
__device__ float g_chog[(size_t)Nn * Mm];
__device__ float g_chfc[(size_t)Nn * Mm];
__device__ float g_chw[(size_t)Nn * Mm];

__device__ int g_parent[Nn];
__device__ int g_depth[Nn];
__device__ int g_order[Nn];
__device__ int g_parorder[Nn];
__device__ int g_lvlstart[256];
__device__ int g_lvlcnt[256];
__device__ int g_maxdepth;

// ---------------- helpers ----------------
__device__ __forceinline__ float sigf(float x) { return 1.f / (1.f + __expf(-x)); }

__device__ __forceinline__ float to_tf32(float x) {
    float r;
    asm("cvt.rna.tf32.f32 %0, %1;" : "=f"(r) : "f"(x));
    return r;
}

__device__ __forceinline__ void mma8(float* c, unsigned a0, unsigned a1, unsigned a2,
                                     unsigned a3, unsigned b0, unsigned b1) {
    asm("mma.sync.aligned.m16n8k8.row.col.f32.tf32.tf32.f32 "
        "{%0,%1,%2,%3}, {%4,%5,%6,%7}, {%8,%9}, {%0,%1,%2,%3};"
        : "+f"(c[0]), "+f"(c[1]), "+f"(c[2]), "+f"(c[3])
        : "r"(a0), "r"(a1), "r"(a2), "r"(a3), "r"(b0), "r"(b1));
}

__device__ __forceinline__ void atomicMaxF(float* addr, float val) {
    int* ia = (int*)addr;
    int old = *ia;
    for (int it = 0; it < 1024 && __int_as_float(old) < val; it++) {
        int assumed = old;
        old = atomicCAS(ia, assumed, __float_as_int(val));
        if (old == assumed) break;
    }
}

// ---------------- tf32 tensor-core GEMM tile: 64 rows x 128 cols, K=512 -----------
// out[orow][c] = sum_k A[arow][k] * W[c][k] + bias[c]
// smem holds fp32 values already converted to tf32, with k permuted inside each
// 8-group so that (k, k+4) fragment pairs are ADJACENT -> all frag reads are LDS.64.
// perm(k): g=k>>3, w=k&7 -> g*8 + (w&3)*2 + (w>>2).
struct __align__(16) SmemG { float As[64][36]; float Bs[128][36]; };

__device__ void gemm_tf32(const float* __restrict__ A,
                          const int* __restrict__ arows,
                          const float* __restrict__ W,
                          const float* __restrict__ bias,
                          float* __restrict__ out,
                          const int* __restrict__ orows,
                          int ldo, int n, int rt, int ct, SmemG* sm) {
    const int tid = threadIdx.x;
    const int lane = tid & 31, warp = tid >> 5;
    const int wr = warp >> 1, wc = warp & 1;          // 4x2 warp grid: 16 rows x 64 cols
    const int grp = lane >> 2, thr = lane & 3;
    const int r0 = rt * 64, c0 = ct * 128;

    // A loader: thread t covers rows (t>>3) and (t>>3)+32, one float4 each per chunk
    const int la_r = tid >> 3;
    const int la_q = tid & 7;                         // float4 index within 32-k chunk
    const int la_g = la_q >> 1, la_a = la_q & 1;
    const int ga0 = r0 + la_r, ga1 = r0 + la_r + 32;
    const bool v0 = ga0 < n, v1 = ga1 < n;
    const float* ap0 = A + (size_t)(v0 ? (arows ? arows[ga0] : ga0) : 0) * 512;
    const float* ap1 = A + (size_t)(v1 ? (arows ? arows[ga1] : ga1) : 0) * 512;

    // B loader: 2 threads per W row, 16 k each (4 float4)
    const int lb_c = tid >> 1;
    const int lb_h = tid & 1;
    const float* wp = W + (size_t)(c0 + lb_c) * 512 + lb_h * 16;

    float c[8][4];
#pragma unroll
    for (int s = 0; s < 8; s++)
#pragma unroll
        for (int j = 0; j < 4; j++) c[s][j] = 0.f;

    for (int k0 = 0; k0 < 512; k0 += 32) {
        // ---- stage A
        {
            float4 x0 = v0 ? *(const float4*)(ap0 + k0 + la_q * 4) : make_float4(0, 0, 0, 0);
            float4 x1 = v1 ? *(const float4*)(ap1 + k0 + la_q * 4) : make_float4(0, 0, 0, 0);
            float* d0 = &sm->As[la_r][la_g * 8 + la_a];
            d0[0] = to_tf32(x0.x); d0[2] = to_tf32(x0.y);
            d0[4] = to_tf32(x0.z); d0[6] = to_tf32(x0.w);
            float* d1 = &sm->As[la_r + 32][la_g * 8 + la_a];
            d1[0] = to_tf32(x1.x); d1[2] = to_tf32(x1.y);
            d1[4] = to_tf32(x1.z); d1[6] = to_tf32(x1.w);
        }
        // ---- stage B (weights)
        {
            float* brow = sm->Bs[lb_c];
#pragma unroll
            for (int m4 = 0; m4 < 4; m4++) {
                float4 x = *(const float4*)(wp + k0 + m4 * 4);
                int kk = lb_h * 16 + m4 * 4;
                float* d = brow + (kk >> 3) * 8 + ((kk >> 2) & 1);
                d[0] = to_tf32(x.x); d[2] = to_tf32(x.y);
                d[4] = to_tf32(x.z); d[6] = to_tf32(x.w);
            }
        }
        __syncthreads();
#pragma unroll
        for (int st = 0; st < 4; st++) {
            const int kk = st * 8;
            float2 a02 = *(float2*)&sm->As[wr * 16 + grp][kk + 2 * thr];
            float2 a13 = *(float2*)&sm->As[wr * 16 + grp + 8][kk + 2 * thr];
            unsigned ua0 = __float_as_uint(a02.x), ua2 = __float_as_uint(a02.y);
            unsigned ua1 = __float_as_uint(a13.x), ua3 = __float_as_uint(a13.y);
#pragma unroll
            for (int s = 0; s < 8; s++) {
                float2 b = *(float2*)&sm->Bs[wc * 64 + s * 8 + grp][kk + 2 * thr];
                mma8(c[s], ua0, ua1, ua2, ua3,
                     __float_as_uint(b.x), __float_as_uint(b.y));
            }
        }
        __syncthreads();
    }

    // ---- epilogue: C frag rows (grp, grp+8), cols (2thr, 2thr+1) per subtile
    const int row_a = r0 + wr * 16 + grp;
    const int row_b = row_a + 8;
    const bool va = row_a < n, vb = row_b < n;
    const int oa = va ? (orows ? orows[row_a] : row_a) : 0;
    const int ob = vb ? (orows ? orows[row_b] : row_b) : 0;
#pragma unroll
    for (int s = 0; s < 8; s++) {
        int cc = c0 + wc * 64 + s * 8 + 2 * thr;
        float2 bv = *(const float2*)(bias + cc);
        if (va) *(float2*)(out + (size_t)oa * ldo + cc) =
            make_float2(c[s][0] + bv.x, c[s][1] + bv.y);
        if (vb) *(float2*)(out + (size_t)ob * ldo + cc) =
            make_float2(c[s][2] + bv.x, c[s][3] + bv.y);
    }
}

// ---------------- setup kernels ----------------
__global__ __launch_bounds__(1024) void k_decode(const void* praw) {
    const int tid = threadIdx.x;
    __shared__ int s_is32;
    if (tid == 0) s_is32 = 0;
    __syncthreads();
    const int* w = (const int*)praw;
    for (int i = tid; i < Nn / 2; i += 1024)
        if (w[2 * i + 1] != 0) atomicOr(&s_is32, 1);
    __syncthreads();
    if (s_is32) {
        for (int i = tid; i < Nn; i += 1024) g_parent[i] = w[i];
    } else {
        const long long* l = (const long long*)praw;
        for (int i = tid; i < Nn; i += 1024) g_parent[i] = (int)l[i];
    }
}

__global__ void k_depth() {
    int idx = blockIdx.x * blockDim.x + threadIdx.x;
    int stride = gridDim.x * blockDim.x;
    for (int i = idx; i < Nn; i += stride) {
        int d = 0, j = i;
        // bounded walk: valid topo-sorted trees terminate in < Nn steps;
        // malformed input cannot hang the container.
        for (int it = 0; it < Nn && j != 0; it++) {
            j = g_parent[j] & (Nn - 1);   // clamp to valid range (8192 -> 0 for root only via j==0 exit)
            d++;
            if (j == 0) break;
        }
        g_depth[i] = d;
    }
}

__global__ __launch_bounds__(1024) void k_levels() {
    const int tid = threadIdx.x;
    __shared__ int s_maxd;
    if (tid == 0) s_maxd = 0;
    for (int d = tid; d < 256; d += 1024) g_lvlcnt[d] = 0;
    __syncthreads();
    int lm = 0;
    for (int i = tid; i < Nn; i += 1024) lm = max(lm, min(g_depth[i], 255));
    atomicMax(&s_maxd, lm);
    __syncthreads();
    if (tid == 0) g_maxdepth = s_maxd;
    for (int i = tid; i < Nn; i += 1024) atomicAdd(&g_lvlcnt[min(g_depth[i], 255)], 1);
    __syncthreads();
    if (tid == 0) {
        int s = 0;
        for (int d = 0; d < 255; d++) { g_lvlstart[d] = s; s += g_lvlcnt[d]; }
        g_lvlstart[255] = s;
    }
    __syncthreads();
    for (int d = tid; d < 256; d += 1024) g_lvlcnt[d] = 0;
    __syncthreads();
    for (int i = tid; i < Nn; i += 1024) {
        int d = min(g_depth[i], 255);
        int pos = atomicAdd(&g_lvlcnt[d], 1);
        g_order[g_lvlstart[d] + pos] = i;
    }
    __syncthreads();
    for (int p = tid; p < Nn; p += 1024) g_parorder[p] = g_parent[g_order[p]];
}

__global__ void k_zero(float* __restrict__ out) {
    size_t idx = (size_t)blockIdx.x * blockDim.x + threadIdx.x;
    size_t stride = (size_t)gridDim.x * blockDim.x;
    const size_t n1 = (size_t)(Nn + 1) * Mm;
    for (size_t i = idx; i < n1; i += stride) {
        g_acch[i] = 0.f; g_accfc[i] = 0.f; g_acczc[i] = 0.f;
    }
    for (size_t i = idx; i < 512; i += stride) out[512 + i] = -1e30f;
}

// ---------------- big input-projection GEMM (px and qx) ----------------
__global__ __launch_bounds__(256) void k_big(const float* __restrict__ x,
                                             const float* __restrict__ csWx,
                                             const float* __restrict__ csbx,
                                             const float* __restrict__ chWx,
                                             const float* __restrict__ chbx) {
    __shared__ SmemG sm;
    int rt = blockIdx.x;   // 0..127
    int ct = blockIdx.y;   // 0..39
    if (ct < 20)
        gemm_tf32(x, nullptr, csWx, csbx, g_px, nullptr, 2560, Nn, rt, ct, &sm);
    else
        gemm_tf32(x, nullptr, chWx, chbx, g_qx, nullptr, 2560, Nn, rt, ct - 20, &sm);
}

// ---------------- superstep kernels ----------------
__global__ __launch_bounds__(256) void k_stage1(int t,
        const float* __restrict__ chWh, const float* __restrict__ chbh,
        const float* __restrict__ csWio, const float* __restrict__ csbio,
        const float* __restrict__ csWum, const float* __restrict__ csbum) {
    __shared__ SmemG sm;
    const int maxd = g_maxdepth;
    const int ct = blockIdx.y;
    if (blockIdx.z == 0) {                        // chain: g = h_parent @ Wh^T + bh
        if (t > maxd) return;
        int s = g_lvlstart[t], n = g_lvlstart[t + 1] - s;
        for (int rt = blockIdx.x; rt * 64 < n; rt += gridDim.x)
            gemm_tf32(g_chh, g_parorder + s, chWh, chbh, g_chg, g_order + s,
                      2048, n, rt, ct, &sm);
    } else {                                      // childsum: io (1024) and w (512)
        int d = maxd - t;
        if (d < 0 || ct >= 12) return;
        int s = g_lvlstart[d], n = g_lvlstart[d + 1] - s;
        for (int rt = blockIdx.x; rt * 64 < n; rt += gridDim.x) {
            if (ct < 8)
                gemm_tf32(g_acch, g_order + s, csWio, csbio, g_csio, g_order + s,
                          1024, n, rt, ct, &sm);
            else
                gemm_tf32(g_acczc, g_order + s, csWum, csbum, g_csw, g_order + s,
                          512, n, rt, ct - 8, &sm);
        }
    }
}

__global__ void k_e1(int t) {
    const int maxd = g_maxdepth;
    int cnt_ch = 0, cs0 = 0;
    if (t <= maxd) { cs0 = g_lvlstart[t]; cnt_ch = g_lvlstart[t + 1] - cs0; }
    int d = maxd - t, cnt_cs = 0, ds0 = 0;
    if (d >= 0) { ds0 = g_lvlstart[d]; cnt_cs = g_lvlstart[d + 1] - ds0; }
    int total = (cnt_ch + cnt_cs) * Mm;
    int idx = blockIdx.x * blockDim.x + threadIdx.x;
    int stride = gridDim.x * blockDim.x;
    for (int e = idx; e < total; e += stride) {
        if (e < cnt_ch * Mm) {
            int r = e >> 9, j = e & 511;
            int node = g_order[cs0 + r];
            int p = g_parent[node];
            const float* q = g_qx + (size_t)node * 2560;
            const float* g = g_chg + (size_t)node * 2048;
            float ig = sigf(q[j] + g[j]);
            float og = sigf(q[512 + j] + g[512 + j]);
            float fg = sigf(q[1024 + j] + g[1024 + j]);
            float zg = sigf(q[1536 + j] + g[1536 + j]);
            float pc = g_chc[(size_t)p * Mm + j];
            size_t nj = (size_t)node * Mm + j;
            g_chs[nj] = zg * tanhf(pc);
            g_chig[nj] = ig; g_chog[nj] = og; g_chfc[nj] = fg * pc;
        } else {
            int k = e - cnt_ch * Mm;
            int r = k >> 9, j = k & 511;
            int node = g_order[ds0 + r];
            const float* px = g_px + (size_t)node * 2560;
            const float* io = g_csio + (size_t)node * 1024;
            size_t nj = (size_t)node * Mm + j;
            float ig = sigf(px[j] + io[j]);
            float og = sigf(px[1024 + j] + io[512 + j]);
            float u = tanhf(px[2048 + j] + g_csw[nj]);
            float c = ig * u + g_accfc[nj];
            float h = og * tanhf(c);
            g_csc[nj] = c; g_csh[nj] = h;
        }
    }
}

__global__ __launch_bounds__(256) void k_stage2(int t,
        const float* __restrict__ chWum, const float* __restrict__ chbum,
        const float* __restrict__ csWfz, const float* __restrict__ csbfz) {
    __shared__ SmemG sm;
    const int maxd = g_maxdepth;
    const int ct = blockIdx.y;
    if (blockIdx.z == 0) {                        // chain: w = s @ Wum^T (512)
        if (t > maxd || ct >= 4) return;
        int s = g_lvlstart[t], n = g_lvlstart[t + 1] - s;
        for (int rt = blockIdx.x; rt * 64 < n; rt += gridDim.x)
            gemm_tf32(g_chs, g_order + s, chWum, chbum, g_chw, g_order + s,
                      512, n, rt, ct, &sm);
    } else {                                      // childsum: fz = h @ Wfz^T (1024)
        int d = maxd - t;
        if (d < 0 || ct >= 8) return;
        int s = g_lvlstart[d], n = g_lvlstart[d + 1] - s;
        for (int rt = blockIdx.x; rt * 64 < n; rt += gridDim.x)
            gemm_tf32(g_csh, g_order + s, csWfz, csbfz, g_csfz, g_order + s,
                      1024, n, rt, ct, &sm);
    }
}

__global__ void k_e2(int t) {
    const int maxd = g_maxdepth;
    int cnt_ch = 0, cs0 = 0;
    if (t <= maxd) { cs0 = g_lvlstart[t]; cnt_ch = g_lvlstart[t + 1] - cs0; }
    int d = maxd - t, cnt_cs = 0, ds0 = 0;
    if (d >= 0) { ds0 = g_lvlstart[d]; cnt_cs = g_lvlstart[d + 1] - ds0; }
    int total = (cnt_ch + cnt_cs) * Mm;
    int idx = blockIdx.x * blockDim.x + threadIdx.x;
    int stride = gridDim.x * blockDim.x;
    for (int e = idx; e < total; e += stride) {
        if (e < cnt_ch * Mm) {
            int r = e >> 9, j = e & 511;
            int node = g_order[cs0 + r];
            size_t nj = (size_t)node * Mm + j;
            float u = tanhf(g_qx[(size_t)node * 2560 + 2048 + j] + g_chw[nj]);
            float c = g_chig[nj] * u + g_chfc[nj];
            float h = g_chog[nj] * tanhf(c);
            g_chc[nj] = c; g_chh[nj] = h;
        } else {
            int k = e - cnt_ch * Mm;
            int r = k >> 9, j = k & 511;
            int node = g_order[ds0 + r];
            int p = g_parent[node];
            size_t nj = (size_t)node * Mm + j;
            const float* fz = g_csfz + (size_t)node * 1024;
            float c = g_csc[nj], h = g_csh[nj];
            float f = sigf(g_px[(size_t)p * 2560 + 512 + j] + fz[j]);
            float z = sigf(g_px[(size_t)p * 2560 + 1536 + j] + fz[512 + j]);
            size_t pj = (size_t)p * Mm + j;
            atomicAdd(&g_acch[pj], h);
            atomicAdd(&g_accfc[pj], f * c);
            atomicAdd(&g_acczc[pj], z * tanhf(c));
        }
    }
}

// ---------------- final: frep = h_root (node 0), brep = colmax(chain h) --------
__global__ void k_final(float* __restrict__ out) {
    int j = threadIdx.x;
    if (blockIdx.x == 32) {
        out[j] = g_csh[j];   // root = node 0
        return;
    }
    int r0 = blockIdx.x * 256;
    float pm = -1e30f;
    for (int r = r0; r < r0 + 256; r++)
        pm = fmaxf(pm, g_chh[(size_t)r * Mm + j]);
    atomicMaxF(out + 512 + j, pm);
}

// ---------------- launch ----------------
extern "C" void kernel_launch(void* const* d_in, const int* in_sizes, int n_in,
                              void* d_out, int out_size) {
    const float* inputs = (const float*)d_in[0];
    const void* parent = d_in[1];
    const float* csWx = (const float*)d_in[2];
    const float* csbx = (const float*)d_in[3];
    const float* csWio = (const float*)d_in[4];
    const float* csbio = (const float*)d_in[5];
    const float* csWfz = (const float*)d_in[6];
    const float* csbfz = (const float*)d_in[7];
    const float* csWum = (const float*)d_in[8];
    const float* csbum = (const float*)d_in[9];
    const float* chWx = (const float*)d_in[10];
    const float* chbx = (const float*)d_in[11];
    const float* chWh = (const float*)d_in[12];
    const float* chbh = (const float*)d_in[13];
    const float* chWum = (const float*)d_in[14];
    const float* chbum = (const float*)d_in[15];
    float* out = (float*)d_out;

    k_decode<<<1, 1024>>>(parent);
    k_depth<<<64, 256>>>();
    k_levels<<<1, 1024>>>();
    k_zero<<<512, 256>>>(out);
    k_big<<<dim3(128, 40), 256>>>(inputs, csWx, csbx, chWx, chbx);
    for (int t = 0; t < TSTEPS; t++) {
        k_stage1<<<dim3(8, 16, 2), 256>>>(t, chWh, chbh, csWio, csbio, csWum, csbum);
        k_e1<<<512, 256>>>(t);
        k_stage2<<<dim3(8, 8, 2), 256>>>(t, chWum, chbum, csWfz, csbfz);
        k_e2<<<512, 256>>>(t);
    }
    k_final<<<33, 512>>>(out);
}

// round 7
// speedup vs baseline: 1.7037x; 1.1747x over previous
#include <cuda_runtime.h>
#include <cstdint>

#define Nn 8192
#define Mm 512

// ---------------- device scratch (static .bss; allocation-free) ----------------
__device__ float g_px[(size_t)(Nn + 1) * 2560];   // childsum x-proj; row Nn stays 0 (sentinel)
__device__ float g_qx[(size_t)Nn * 2560];         // chain x-proj
__device__ float g_acch[(size_t)(Nn + 1) * Mm];
__device__ float g_accfc[(size_t)(Nn + 1) * Mm];
__device__ float g_acczc[(size_t)(Nn + 1) * Mm];
__device__ float g_csc[(size_t)Nn * Mm];
__device__ float g_csh[(size_t)Nn * Mm];
__device__ float g_chc[(size_t)(Nn + 1) * Mm];    // row Nn stays 0 forever (root's phantom)
__device__ float g_chh[(size_t)(Nn + 1) * Mm];    // row Nn stays 0 forever
__device__ float g_csio[(size_t)Nn * 1024];
__device__ float g_csw[(size_t)Nn * Mm];
__device__ float g_csfz[(size_t)Nn * 1024];
__device__ float g_chg[(size_t)Nn * 2048];
__device__ float g_chs[(size_t)Nn * Mm];
__device__ float g_chig[(size_t)Nn * Mm];
__device__ float g_chog[(size_t)Nn * Mm];
__device__ float g_chfc[(size_t)Nn * Mm];
__device__ float g_chw[(size_t)Nn * Mm];

__device__ int g_parent[Nn];
__device__ int g_depth[Nn];
__device__ int g_order[Nn];
__device__ int g_parorder[Nn];
__device__ int g_lvlstart[256];
__device__ int g_lvlcnt[256];
__device__ int g_maxdepth;

__device__ unsigned g_barcnt;   // zero-init; returns to 0 after every barrier
__device__ unsigned g_bargen;   // monotonically increasing generation

// ---------------- helpers ----------------
__device__ __forceinline__ float sigf(float x) { return 1.f / (1.f + __expf(-x)); }

__device__ __forceinline__ float to_tf32(float x) {
    float r;
    asm("cvt.rna.tf32.f32 %0, %1;" : "=f"(r) : "f"(x));
    return r;
}

__device__ __forceinline__ void mma8(float* c, unsigned a0, unsigned a1, unsigned a2,
                                     unsigned a3, unsigned b0, unsigned b1) {
    asm("mma.sync.aligned.m16n8k8.row.col.f32.tf32.tf32.f32 "
        "{%0,%1,%2,%3}, {%4,%5,%6,%7}, {%8,%9}, {%0,%1,%2,%3};"
        : "+f"(c[0]), "+f"(c[1]), "+f"(c[2]), "+f"(c[3])
        : "r"(a0), "r"(a1), "r"(a2), "r"(a3), "r"(b0), "r"(b1));
}

__device__ __forceinline__ void atomicMaxF(float* addr, float val) {
    int* ia = (int*)addr;
    int old = *ia;
    for (int it = 0; it < 1024 && __int_as_float(old) < val; it++) {
        int assumed = old;
        old = atomicCAS(ia, assumed, __float_as_int(val));
        if (old == assumed) break;
    }
}

// grid-wide barrier; all gridDim.x blocks are guaranteed co-resident (occupancy
// checked at launch). Bounded spin: a logic bug degrades to wrong-answer, not a
// container-wedging hang.
__device__ __forceinline__ void gsync() {
    __syncthreads();
    if (threadIdx.x == 0) {
        __threadfence();
        volatile unsigned* vgen = &g_bargen;
        unsigned gen = *vgen;
        if (atomicAdd(&g_barcnt, 1u) == gridDim.x - 1) {
            atomicExch(&g_barcnt, 0u);
            __threadfence();
            atomicAdd(&g_bargen, 1u);
        } else {
            long long spins = 0;
            while (*vgen == gen && spins < 300000000LL) { __nanosleep(128); spins++; }
            __threadfence();
        }
    }
    __syncthreads();
}

// ---------------- tf32 tensor-core GEMM tile: 64 rows x 128 cols, K=512 -----------
// out[orow][c] = sum_k A[arow][k] * W[c][k] + bias[c]
// smem holds fp32 values already converted to tf32, with k permuted inside each
// 8-group so that (k, k+4) fragment pairs are ADJACENT -> all frag reads are LDS.64.
struct __align__(16) SmemG { float As[64][36]; float Bs[128][36]; };

__device__ void gemm_tf32(const float* __restrict__ A,
                          const int* __restrict__ arows,
                          const float* __restrict__ W,
                          const float* __restrict__ bias,
                          float* __restrict__ out,
                          const int* __restrict__ orows,
                          int ldo, int n, int rt, int ct, SmemG* sm) {
    const int tid = threadIdx.x;
    const int lane = tid & 31, warp = tid >> 5;
    const int wr = warp >> 1, wc = warp & 1;          // 4x2 warp grid: 16 rows x 64 cols
    const int grp = lane >> 2, thr = lane & 3;
    const int r0 = rt * 64, c0 = ct * 128;

    const int la_r = tid >> 3;
    const int la_q = tid & 7;                         // float4 index within 32-k chunk
    const int la_g = la_q >> 1, la_a = la_q & 1;
    const int ga0 = r0 + la_r, ga1 = r0 + la_r + 32;
    const bool v0 = ga0 < n, v1 = ga1 < n;
    const float* ap0 = A + (size_t)(v0 ? (arows ? arows[ga0] : ga0) : 0) * 512;
    const float* ap1 = A + (size_t)(v1 ? (arows ? arows[ga1] : ga1) : 0) * 512;

    const int lb_c = tid >> 1;
    const int lb_h = tid & 1;
    const float* wp = W + (size_t)(c0 + lb_c) * 512 + lb_h * 16;

    float c[8][4];
#pragma unroll
    for (int s = 0; s < 8; s++)
#pragma unroll
        for (int j = 0; j < 4; j++) c[s][j] = 0.f;

    for (int k0 = 0; k0 < 512; k0 += 32) {
        {
            float4 x0 = v0 ? *(const float4*)(ap0 + k0 + la_q * 4) : make_float4(0, 0, 0, 0);
            float4 x1 = v1 ? *(const float4*)(ap1 + k0 + la_q * 4) : make_float4(0, 0, 0, 0);
            float* d0 = &sm->As[la_r][la_g * 8 + la_a];
            d0[0] = to_tf32(x0.x); d0[2] = to_tf32(x0.y);
            d0[4] = to_tf32(x0.z); d0[6] = to_tf32(x0.w);
            float* d1 = &sm->As[la_r + 32][la_g * 8 + la_a];
            d1[0] = to_tf32(x1.x); d1[2] = to_tf32(x1.y);
            d1[4] = to_tf32(x1.z); d1[6] = to_tf32(x1.w);
        }
        {
            float* brow = sm->Bs[lb_c];
#pragma unroll
            for (int m4 = 0; m4 < 4; m4++) {
                float4 x = *(const float4*)(wp + k0 + m4 * 4);
                int kk = lb_h * 16 + m4 * 4;
                float* d = brow + (kk >> 3) * 8 + ((kk >> 2) & 1);
                d[0] = to_tf32(x.x); d[2] = to_tf32(x.y);
                d[4] = to_tf32(x.z); d[6] = to_tf32(x.w);
            }
        }
        __syncthreads();
#pragma unroll
        for (int st = 0; st < 4; st++) {
            const int kk = st * 8;
            float2 a02 = *(float2*)&sm->As[wr * 16 + grp][kk + 2 * thr];
            float2 a13 = *(float2*)&sm->As[wr * 16 + grp + 8][kk + 2 * thr];
            unsigned ua0 = __float_as_uint(a02.x), ua2 = __float_as_uint(a02.y);
            unsigned ua1 = __float_as_uint(a13.x), ua3 = __float_as_uint(a13.y);
#pragma unroll
            for (int s = 0; s < 8; s++) {
                float2 b = *(float2*)&sm->Bs[wc * 64 + s * 8 + grp][kk + 2 * thr];
                mma8(c[s], ua0, ua1, ua2, ua3,
                     __float_as_uint(b.x), __float_as_uint(b.y));
            }
        }
        __syncthreads();
    }

    const int row_a = r0 + wr * 16 + grp;
    const int row_b = row_a + 8;
    const bool va = row_a < n, vb = row_b < n;
    const int oa = va ? (orows ? orows[row_a] : row_a) : 0;
    const int ob = vb ? (orows ? orows[row_b] : row_b) : 0;
#pragma unroll
    for (int s = 0; s < 8; s++) {
        int cc = c0 + wc * 64 + s * 8 + 2 * thr;
        float2 bv = *(const float2*)(bias + cc);
        if (va) *(float2*)(out + (size_t)oa * ldo + cc) =
            make_float2(c[s][0] + bv.x, c[s][1] + bv.y);
        if (vb) *(float2*)(out + (size_t)ob * ldo + cc) =
            make_float2(c[s][2] + bv.x, c[s][3] + bv.y);
    }
}

// ---------------- setup kernels ----------------
__global__ __launch_bounds__(1024) void k_decode(const void* praw) {
    const int tid = threadIdx.x;
    __shared__ int s_is32;
    if (tid == 0) s_is32 = 0;
    __syncthreads();
    const int* w = (const int*)praw;
    for (int i = tid; i < Nn / 2; i += 1024)
        if (w[2 * i + 1] != 0) atomicOr(&s_is32, 1);
    __syncthreads();
    if (s_is32) {
        for (int i = tid; i < Nn; i += 1024) g_parent[i] = w[i];
    } else {
        const long long* l = (const long long*)praw;
        for (int i = tid; i < Nn; i += 1024) g_parent[i] = (int)l[i];
    }
}

__global__ void k_depth() {
    int idx = blockIdx.x * blockDim.x + threadIdx.x;
    int stride = gridDim.x * blockDim.x;
    for (int i = idx; i < Nn; i += stride) {
        int d = 0, j = i;
        for (int it = 0; it < Nn && j != 0; it++) {
            j = g_parent[j] & (Nn - 1);
            d++;
            if (j == 0) break;
        }
        g_depth[i] = d;
    }
}

__global__ __launch_bounds__(1024) void k_levels() {
    const int tid = threadIdx.x;
    __shared__ int s_maxd;
    if (tid == 0) s_maxd = 0;
    for (int d = tid; d < 256; d += 1024) g_lvlcnt[d] = 0;
    __syncthreads();
    int lm = 0;
    for (int i = tid; i < Nn; i += 1024) lm = max(lm, min(g_depth[i], 255));
    atomicMax(&s_maxd, lm);
    __syncthreads();
    if (tid == 0) g_maxdepth = s_maxd;
    for (int i = tid; i < Nn; i += 1024) atomicAdd(&g_lvlcnt[min(g_depth[i], 255)], 1);
    __syncthreads();
    if (tid == 0) {
        int s = 0;
        for (int d = 0; d < 255; d++) { g_lvlstart[d] = s; s += g_lvlcnt[d]; }
        g_lvlstart[255] = s;
    }
    __syncthreads();
    for (int d = tid; d < 256; d += 1024) g_lvlcnt[d] = 0;
    __syncthreads();
    for (int i = tid; i < Nn; i += 1024) {
        int d = min(g_depth[i], 255);
        int pos = atomicAdd(&g_lvlcnt[d], 1);
        g_order[g_lvlstart[d] + pos] = i;
    }
    __syncthreads();
    for (int p = tid; p < Nn; p += 1024) g_parorder[p] = g_parent[g_order[p]];
}

// ---------------- the persistent mega-kernel ----------------
__global__ __launch_bounds__(256, 2) void k_mega(
        const float* __restrict__ x,
        const float* __restrict__ csWx, const float* __restrict__ csbx,
        const float* __restrict__ csWio, const float* __restrict__ csbio,
        const float* __restrict__ csWfz, const float* __restrict__ csbfz,
        const float* __restrict__ csWum, const float* __restrict__ csbum,
        const float* __restrict__ chWx, const float* __restrict__ chbx,
        const float* __restrict__ chWh, const float* __restrict__ chbh,
        const float* __restrict__ chWum, const float* __restrict__ chbum,
        float* __restrict__ out) {
    __shared__ SmemG sm;
    const int bid = blockIdx.x, nb = gridDim.x;
    const int tid = threadIdx.x;
    const int gidx = bid * 256 + tid, gstride = nb * 256;
    const int maxd = g_maxdepth;

    // ---- phase 0: zero accumulators, init out max region, big input GEMMs ----
    {
        const size_t n1 = (size_t)(Nn + 1) * Mm;
        for (size_t i = gidx; i < n1; i += gstride) {
            g_acch[i] = 0.f; g_accfc[i] = 0.f; g_acczc[i] = 0.f;
        }
        if (gidx < 512) out[512 + gidx] = -1e30f;
    }
    for (int tile = bid; tile < 5120; tile += nb) {
        int rt = tile & 127, ct = tile >> 7;          // 128 row-tiles x 40 col-tiles
        if (ct < 20)
            gemm_tf32(x, nullptr, csWx, csbx, g_px, nullptr, 2560, Nn, rt, ct, &sm);
        else
            gemm_tf32(x, nullptr, chWx, chbx, g_qx, nullptr, 2560, Nn, rt, ct - 20, &sm);
    }
    gsync();

    // ---- superstep loop: chain level t  +  childsum level (maxd - t) ----
    for (int t = 0; t <= maxd; t++) {
        const int s_ch = g_lvlstart[t];
        const int n_ch = g_lvlstart[t + 1] - s_ch;
        const int d = maxd - t;
        const int s_cs = g_lvlstart[d];
        const int n_cs = g_lvlstart[d + 1] - s_cs;
        const int rt_ch = (n_ch + 63) >> 6;
        const int rt_cs = (n_cs + 63) >> 6;

        // stage1: chain g = h_par @ Wh^T (2048 cols); childsum io (1024) + w (512)
        {
            const int t_ch = rt_ch * 16, t_cs = rt_cs * 12;
            for (int i = bid; i < t_ch + t_cs; i += nb) {
                if (i < t_ch) {
                    gemm_tf32(g_chh, g_parorder + s_ch, chWh, chbh, g_chg,
                              g_order + s_ch, 2048, n_ch, i >> 4, i & 15, &sm);
                } else {
                    int j = i - t_ch, rt = j / 12, ct = j % 12;
                    if (ct < 8)
                        gemm_tf32(g_acch, g_order + s_cs, csWio, csbio, g_csio,
                                  g_order + s_cs, 1024, n_cs, rt, ct, &sm);
                    else
                        gemm_tf32(g_acczc, g_order + s_cs, csWum, csbum, g_csw,
                                  g_order + s_cs, 512, n_cs, rt, ct - 8, &sm);
                }
            }
        }
        gsync();

        // e1
        {
            const int total = (n_ch + n_cs) * Mm;
            for (int e = gidx; e < total; e += gstride) {
                if (e < n_ch * Mm) {
                    int r = e >> 9, j = e & 511;
                    int node = g_order[s_ch + r];
                    int p = g_parent[node];
                    const float* q = g_qx + (size_t)node * 2560;
                    const float* g = g_chg + (size_t)node * 2048;
                    float ig = sigf(q[j] + g[j]);
                    float og = sigf(q[512 + j] + g[512 + j]);
                    float fg = sigf(q[1024 + j] + g[1024 + j]);
                    float zg = sigf(q[1536 + j] + g[1536 + j]);
                    float pc = g_chc[(size_t)p * Mm + j];
                    size_t nj = (size_t)node * Mm + j;
                    g_chs[nj] = zg * tanhf(pc);
                    g_chig[nj] = ig; g_chog[nj] = og; g_chfc[nj] = fg * pc;
                } else {
                    int k = e - n_ch * Mm;
                    int r = k >> 9, j = k & 511;
                    int node = g_order[s_cs + r];
                    const float* px = g_px + (size_t)node * 2560;
                    const float* io = g_csio + (size_t)node * 1024;
                    size_t nj = (size_t)node * Mm + j;
                    float ig = sigf(px[j] + io[j]);
                    float og = sigf(px[1024 + j] + io[512 + j]);
                    float u = tanhf(px[2048 + j] + g_csw[nj]);
                    float c = ig * u + g_accfc[nj];
                    float h = og * tanhf(c);
                    g_csc[nj] = c; g_csh[nj] = h;
                }
            }
        }
        gsync();

        // stage2: chain w = s @ Wum^T (512); childsum fz = h @ Wfz^T (1024)
        {
            const int u_ch = rt_ch * 4, u_cs = rt_cs * 8;
            for (int i = bid; i < u_ch + u_cs; i += nb) {
                if (i < u_ch)
                    gemm_tf32(g_chs, g_order + s_ch, chWum, chbum, g_chw,
                              g_order + s_ch, 512, n_ch, i >> 2, i & 3, &sm);
                else {
                    int j = i - u_ch;
                    gemm_tf32(g_csh, g_order + s_cs, csWfz, csbfz, g_csfz,
                              g_order + s_cs, 1024, n_cs, j >> 3, j & 7, &sm);
                }
            }
        }
        gsync();

        // e2
        {
            const int total = (n_ch + n_cs) * Mm;
            for (int e = gidx; e < total; e += gstride) {
                if (e < n_ch * Mm) {
                    int r = e >> 9, j = e & 511;
                    int node = g_order[s_ch + r];
                    size_t nj = (size_t)node * Mm + j;
                    float u = tanhf(g_qx[(size_t)node * 2560 + 2048 + j] + g_chw[nj]);
                    float c = g_chig[nj] * u + g_chfc[nj];
                    float h = g_chog[nj] * tanhf(c);
                    g_chc[nj] = c; g_chh[nj] = h;
                } else {
                    int k = e - n_ch * Mm;
                    int r = k >> 9, j = k & 511;
                    int node = g_order[s_cs + r];
                    int p = g_parent[node];
                    size_t nj = (size_t)node * Mm + j;
                    const float* fz = g_csfz + (size_t)node * 1024;
                    float c = g_csc[nj], h = g_csh[nj];
                    float f = sigf(g_px[(size_t)p * 2560 + 512 + j] + fz[j]);
                    float z = sigf(g_px[(size_t)p * 2560 + 1536 + j] + fz[512 + j]);
                    size_t pj = (size_t)p * Mm + j;
                    atomicAdd(&g_acch[pj], h);
                    atomicAdd(&g_accfc[pj], f * c);
                    atomicAdd(&g_acczc[pj], z * tanhf(c));
                }
            }
        }
        gsync();
    }

    // ---- final: frep = h_root (node 0), brep = colmax(chain h) ----
    if (bid < 32) {
        float m0 = -1e30f, m1 = -1e30f;
        const int r0 = bid * 256, r1 = r0 + 256;
        for (int r = r0; r < r1; r++) {
            m0 = fmaxf(m0, g_chh[(size_t)r * Mm + tid]);
            m1 = fmaxf(m1, g_chh[(size_t)r * Mm + 256 + tid]);
        }
        atomicMaxF(out + 512 + tid, m0);
        atomicMaxF(out + 768 + tid, m1);
    } else if (bid == 32) {
        out[tid] = g_csh[tid];
        out[256 + tid] = g_csh[256 + tid];
    }
}

// ---------------- launch ----------------
extern "C" void kernel_launch(void* const* d_in, const int* in_sizes, int n_in,
                              void* d_out, int out_size) {
    const float* inputs = (const float*)d_in[0];
    const void* parent = d_in[1];
    const float* csWx = (const float*)d_in[2];
    const float* csbx = (const float*)d_in[3];
    const float* csWio = (const float*)d_in[4];
    const float* csbio = (const float*)d_in[5];
    const float* csWfz = (const float*)d_in[6];
    const float* csbfz = (const float*)d_in[7];
    const float* csWum = (const float*)d_in[8];
    const float* csbum = (const float*)d_in[9];
    const float* chWx = (const float*)d_in[10];
    const float* chbx = (const float*)d_in[11];
    const float* chWh = (const float*)d_in[12];
    const float* chbh = (const float*)d_in[13];
    const float* chWum = (const float*)d_in[14];
    const float* chbum = (const float*)d_in[15];
    float* out = (float*)d_out;

    // co-residency guarantee for the grid barrier (pure query; no allocation)
    int occ = 1;
    cudaOccupancyMaxActiveBlocksPerMultiprocessor(&occ, k_mega, 256, 0);
    if (occ < 1) occ = 1;
    int smcount = 148;
    cudaDeviceGetAttribute(&smcount, cudaDevAttrMultiProcessorCount, 0);
    int nb = smcount * (occ < 2 ? occ : 2);
    if (nb < 33) nb = 33;   // final phase needs 33 blocks (always true in practice)

    k_decode<<<1, 1024>>>(parent);
    k_depth<<<64, 256>>>();
    k_levels<<<1, 1024>>>();
    k_mega<<<nb, 256>>>(inputs, csWx, csbx, csWio, csbio, csWfz, csbfz,
                        csWum, csbum, chWx, chbx, chWh, chbh, chWum, chbum, out);
}

// round 9
// speedup vs baseline: 2.2905x; 1.3444x over previous
#include <cuda_runtime.h>
#include <cstdint>

#define Nn 8192
#define Mm 512

// ---------------- device scratch (static .bss; allocation-free) ----------------
__device__ float g_px[(size_t)(Nn + 1) * 2560];   // childsum x-proj; row Nn stays 0 (sentinel)
__device__ float g_qx[(size_t)Nn * 2560];         // chain x-proj
__device__ float g_acch[(size_t)(Nn + 1) * Mm];
__device__ float g_accfc[(size_t)(Nn + 1) * Mm];
__device__ float g_acczc[(size_t)(Nn + 1) * Mm];
__device__ float g_csc[(size_t)Nn * Mm];
__device__ float g_csh[(size_t)Nn * Mm];
__device__ float g_chc[(size_t)(Nn + 1) * Mm];    // row Nn stays 0 forever (root's phantom)
__device__ float g_chh[(size_t)(Nn + 1) * Mm];    // row Nn stays 0 forever
__device__ float g_csio[(size_t)Nn * 1024];
__device__ float g_csw[(size_t)Nn * Mm];
__device__ float g_csfz[(size_t)Nn * 1024];
__device__ float g_chg[(size_t)Nn * 2048];
__device__ float g_chs[(size_t)Nn * Mm];
__device__ float g_chig[(size_t)Nn * Mm];
__device__ float g_chog[(size_t)Nn * Mm];
__device__ float g_chfc[(size_t)Nn * Mm];
__device__ float g_chw[(size_t)Nn * Mm];

// pre-converted weight tile images: 80 tiles x 16 chunks x 128 rows x 36 floats
// (tf32-converted, k-permuted, 36-stride == exact smem image for the B buffer)
#define TILE_IMG 73728            // 16*128*36
__device__ __align__(16) float g_wt[(size_t)80 * TILE_IMG];
// tile bases
#define T_CHWH  0
#define T_CSWIO 16
#define T_CSWUM 24
#define T_CHWUM 28
#define T_CSWFZ 32
#define T_CSWX  40
#define T_CHWX  60

__device__ int g_parent[Nn];
__device__ int g_depth[Nn];
__device__ int g_order[Nn];
__device__ int g_parorder[Nn];
__device__ int g_lvlstart[256];
__device__ int g_lvlcnt[256];
__device__ int g_maxdepth;

__device__ unsigned g_barcnt;
__device__ unsigned g_bargen;

// ---------------- helpers ----------------
__device__ __forceinline__ float sigf(float x) { return 1.f / (1.f + __expf(-x)); }

__device__ __forceinline__ float to_tf32(float x) {
    float r;
    asm("cvt.rna.tf32.f32 %0, %1;" : "=f"(r) : "f"(x));
    return r;
}

__device__ __forceinline__ void mma8(float* c, unsigned a0, unsigned a1, unsigned a2,
                                     unsigned a3, unsigned b0, unsigned b1) {
    asm("mma.sync.aligned.m16n8k8.row.col.f32.tf32.tf32.f32 "
        "{%0,%1,%2,%3}, {%4,%5,%6,%7}, {%8,%9}, {%0,%1,%2,%3};"
        : "+f"(c[0]), "+f"(c[1]), "+f"(c[2]), "+f"(c[3])
        : "r"(a0), "r"(a1), "r"(a2), "r"(a3), "r"(b0), "r"(b1));
}

__device__ __forceinline__ void cp16(uint32_t dst, const void* src) {
    asm volatile("cp.async.ca.shared.global [%0], [%1], 16;" :: "r"(dst), "l"(src));
}

__device__ __forceinline__ void atomicMaxF(float* addr, float val) {
    int* ia = (int*)addr;
    int old = *ia;
    for (int it = 0; it < 1024 && __int_as_float(old) < val; it++) {
        int assumed = old;
        old = atomicCAS(ia, assumed, __float_as_int(val));
        if (old == assumed) break;
    }
}

// grid-wide barrier (all blocks co-resident; bounded spin so bugs can't wedge)
__device__ __forceinline__ void gsync() {
    __syncthreads();
    if (threadIdx.x == 0) {
        __threadfence();
        volatile unsigned* vgen = &g_bargen;
        unsigned gen = *vgen;
        if (atomicAdd(&g_barcnt, 1u) == gridDim.x - 1) {
            atomicExch(&g_barcnt, 0u);
            __threadfence();
            atomicAdd(&g_bargen, 1u);
        } else {
            long long spins = 0;
            while (*vgen == gen && spins < 300000000LL) { __nanosleep(128); spins++; }
            __threadfence();
        }
    }
    __syncthreads();
}

// ---------------- pipelined tf32 GEMM tile: 64 rows x 128 cols, K=512 ------------
// B from pre-built weight images via double-buffered cp.async;
// A via register prefetch + cvt/permute STS. k-permutation: pos = g*8 + a + 2*j
// for k = g*8 + a*4 + j  -> fragment (k, k+4) pairs adjacent -> LDS.64.
struct __align__(16) SmemG { float As[64][36]; float Bs[2][4608]; };

__device__ void gemm_tf32(const float* __restrict__ A,
                          const int* __restrict__ arows,
                          int wbase,
                          const float* __restrict__ bias,
                          float* __restrict__ out,
                          const int* __restrict__ orows,
                          int ldo, int n, int rt, int ct, SmemG* sm) {
    const int tid = threadIdx.x;
    const int lane = tid & 31, warp = tid >> 5;
    const int wr = warp >> 1, wc = warp & 1;          // 4x2 warp grid: 16 rows x 64 cols
    const int grp = lane >> 2, thr = lane & 3;
    const int r0 = rt * 64, c0 = ct * 128;

    const int la_r = tid >> 3;
    const int la_q = tid & 7;
    const int la_g = la_q >> 1, la_a = la_q & 1;
    const int ga0 = r0 + la_r, ga1 = r0 + la_r + 32;
    const bool v0 = ga0 < n, v1 = ga1 < n;
    const float* ap0 = A + (size_t)(v0 ? (arows ? arows[ga0] : ga0) : 0) * 512;
    const float* ap1 = A + (size_t)(v1 ? (arows ? arows[ga1] : ga1) : 0) * 512;

    const float* wsrc = g_wt + (size_t)(wbase + ct) * TILE_IMG;
    uint32_t bsaddr0 = (uint32_t)__cvta_generic_to_shared(&sm->Bs[0][0]);
    uint32_t bsaddr1 = (uint32_t)__cvta_generic_to_shared(&sm->Bs[1][0]);

    float c[8][4];
#pragma unroll
    for (int s = 0; s < 8; s++)
#pragma unroll
        for (int j = 0; j < 4; j++) c[s][j] = 0.f;

    // prologue: A chunk0 regs + B chunk0 cp.async
    float4 a0 = v0 ? *(const float4*)(ap0 + la_q * 4) : make_float4(0, 0, 0, 0);
    float4 a1 = v1 ? *(const float4*)(ap1 + la_q * 4) : make_float4(0, 0, 0, 0);
    {
        const char* src = (const char*)wsrc;
#pragma unroll
        for (int off = 0; off < 18432; off += 4096) {
            int o = off + tid * 16;
            if (o < 18432) cp16(bsaddr0 + o, src + o);
        }
        asm volatile("cp.async.commit_group;");
    }

#pragma unroll 1
    for (int i = 0; i < 16; i++) {
        // store A chunk i (permuted + tf32)
        {
            float* d0 = &sm->As[la_r][la_g * 8 + la_a];
            d0[0] = to_tf32(a0.x); d0[2] = to_tf32(a0.y);
            d0[4] = to_tf32(a0.z); d0[6] = to_tf32(a0.w);
            float* d1 = &sm->As[la_r + 32][la_g * 8 + la_a];
            d1[0] = to_tf32(a1.x); d1[2] = to_tf32(a1.y);
            d1[4] = to_tf32(a1.z); d1[6] = to_tf32(a1.w);
        }
        asm volatile("cp.async.wait_group 0;");
        __syncthreads();

        // launch next chunk's loads (overlap with MMAs below)
        if (i < 15) {
            a0 = v0 ? *(const float4*)(ap0 + (i + 1) * 32 + la_q * 4) : make_float4(0, 0, 0, 0);
            a1 = v1 ? *(const float4*)(ap1 + (i + 1) * 32 + la_q * 4) : make_float4(0, 0, 0, 0);
            const char* src = (const char*)(wsrc + (size_t)(i + 1) * 4608);
            uint32_t db = ((i + 1) & 1) ? bsaddr1 : bsaddr0;
#pragma unroll
            for (int off = 0; off < 18432; off += 4096) {
                int o = off + tid * 16;
                if (o < 18432) cp16(db + o, src + o);
            }
            asm volatile("cp.async.commit_group;");
        }

        const float* bcur = (i & 1) ? &sm->Bs[1][0] : &sm->Bs[0][0];
#pragma unroll
        for (int st = 0; st < 4; st++) {
            const int kk = st * 8;
            float2 a02 = *(float2*)&sm->As[wr * 16 + grp][kk + 2 * thr];
            float2 a13 = *(float2*)&sm->As[wr * 16 + grp + 8][kk + 2 * thr];
            unsigned ua0 = __float_as_uint(a02.x), ua2 = __float_as_uint(a02.y);
            unsigned ua1 = __float_as_uint(a13.x), ua3 = __float_as_uint(a13.y);
#pragma unroll
            for (int s = 0; s < 8; s++) {
                float2 b = *(float2*)&bcur[(wc * 64 + s * 8 + grp) * 36 + kk + 2 * thr];
                mma8(c[s], ua0, ua1, ua2, ua3,
                     __float_as_uint(b.x), __float_as_uint(b.y));
            }
        }
        __syncthreads();
    }

    const int row_a = r0 + wr * 16 + grp;
    const int row_b = row_a + 8;
    const bool va = row_a < n, vb = row_b < n;
    const int oa = va ? (orows ? orows[row_a] : row_a) : 0;
    const int ob = vb ? (orows ? orows[row_b] : row_b) : 0;
#pragma unroll
    for (int s = 0; s < 8; s++) {
        int cc = c0 + wc * 64 + s * 8 + 2 * thr;
        float2 bv = *(const float2*)(bias + cc);
        if (va) *(float2*)(out + (size_t)oa * ldo + cc) =
            make_float2(c[s][0] + bv.x, c[s][1] + bv.y);
        if (vb) *(float2*)(out + (size_t)ob * ldo + cc) =
            make_float2(c[s][2] + bv.x, c[s][3] + bv.y);
    }
}

// ---------------- setup kernels ----------------
__global__ __launch_bounds__(1024) void k_decode(const void* praw) {
    const int tid = threadIdx.x;
    __shared__ int s_is32;
    if (tid == 0) s_is32 = 0;
    __syncthreads();
    const int* w = (const int*)praw;
    for (int i = tid; i < Nn / 2; i += 1024)
        if (w[2 * i + 1] != 0) atomicOr(&s_is32, 1);
    __syncthreads();
    if (s_is32) {
        for (int i = tid; i < Nn; i += 1024) g_parent[i] = w[i];
    } else {
        const long long* l = (const long long*)praw;
        for (int i = tid; i < Nn; i += 1024) g_parent[i] = (int)l[i];
    }
}

__global__ void k_depth() {
    int idx = blockIdx.x * blockDim.x + threadIdx.x;
    int stride = gridDim.x * blockDim.x;
    for (int i = idx; i < Nn; i += stride) {
        int d = 0, j = i;
        for (int it = 0; it < Nn && j != 0; it++) {
            j = g_parent[j] & (Nn - 1);
            d++;
            if (j == 0) break;
        }
        g_depth[i] = d;
    }
}

__global__ __launch_bounds__(1024) void k_levels() {
    const int tid = threadIdx.x;
    __shared__ int s_maxd;
    if (tid == 0) s_maxd = 0;
    for (int d = tid; d < 256; d += 1024) g_lvlcnt[d] = 0;
    __syncthreads();
    int lm = 0;
    for (int i = tid; i < Nn; i += 1024) lm = max(lm, min(g_depth[i], 255));
    atomicMax(&s_maxd, lm);
    __syncthreads();
    if (tid == 0) g_maxdepth = s_maxd;
    for (int i = tid; i < Nn; i += 1024) atomicAdd(&g_lvlcnt[min(g_depth[i], 255)], 1);
    __syncthreads();
    if (tid == 0) {
        int s = 0;
        for (int d = 0; d < 255; d++) { g_lvlstart[d] = s; s += g_lvlcnt[d]; }
        g_lvlstart[255] = s;
    }
    __syncthreads();
    for (int d = tid; d < 256; d += 1024) g_lvlcnt[d] = 0;
    __syncthreads();
    for (int i = tid; i < Nn; i += 1024) {
        int d = min(g_depth[i], 255);
        int pos = atomicAdd(&g_lvlcnt[d], 1);
        g_order[g_lvlstart[d] + pos] = i;
    }
    __syncthreads();
    for (int p = tid; p < Nn; p += 1024) g_parorder[p] = g_parent[g_order[p]];
}

// ---------------- the persistent mega-kernel ----------------
__global__ __launch_bounds__(256, 2) void k_mega(
        const float* __restrict__ x,
        const float* __restrict__ csWx, const float* __restrict__ csbx,
        const float* __restrict__ csWio, const float* __restrict__ csbio,
        const float* __restrict__ csWfz, const float* __restrict__ csbfz,
        const float* __restrict__ csWum, const float* __restrict__ csbum,
        const float* __restrict__ chWx, const float* __restrict__ chbx,
        const float* __restrict__ chWh, const float* __restrict__ chbh,
        const float* __restrict__ chWum, const float* __restrict__ chbum,
        float* __restrict__ out) {
    __shared__ SmemG sm;
    const int bid = blockIdx.x, nb = gridDim.x;
    const int tid = threadIdx.x;
    const int gidx = bid * 256 + tid, gstride = nb * 256;
    const int maxd = g_maxdepth;

    // ---- phase -1: build weight tile images + zero accumulators ----
    {
        const size_t n1 = (size_t)(Nn + 1) * Mm;
        for (size_t i = gidx; i < n1; i += gstride) {
            g_acch[i] = 0.f; g_accfc[i] = 0.f; g_acczc[i] = 0.f;
        }
        if (gidx < 512) out[512 + gidx] = -1e30f;

        const size_t total = (size_t)80 * TILE_IMG;
        for (size_t idx = gidx; idx < total; idx += gstride) {
            int t = (int)(idx / TILE_IMG);
            int r = (int)(idx % TILE_IMG);
            int chunk = r / 4608;
            int rem = r % 4608;
            int row = rem / 36;
            int pos = rem % 36;
            float v = 0.f;
            if (pos < 32) {
                int g = pos >> 3, q = pos & 7;
                int kk = g * 8 + (q & 1) * 4 + (q >> 1);
                const float* W; int tc;
                if (t < 16)      { W = chWh;  tc = t; }
                else if (t < 24) { W = csWio; tc = t - 16; }
                else if (t < 28) { W = csWum; tc = t - 24; }
                else if (t < 32) { W = chWum; tc = t - 28; }
                else if (t < 40) { W = csWfz; tc = t - 32; }
                else if (t < 60) { W = csWx;  tc = t - 40; }
                else             { W = chWx;  tc = t - 60; }
                v = to_tf32(W[(size_t)(tc * 128 + row) * 512 + chunk * 32 + kk]);
            }
            g_wt[idx] = v;
        }
    }
    gsync();

    // ---- phase 0: big input GEMMs ----
    for (int tile = bid; tile < 5120; tile += nb) {
        int rt = tile & 127, ct = tile >> 7;          // 128 row-tiles x 40 col-tiles
        if (ct < 20)
            gemm_tf32(x, nullptr, T_CSWX, csbx, g_px, nullptr, 2560, Nn, rt, ct, &sm);
        else
            gemm_tf32(x, nullptr, T_CHWX, chbx, g_qx, nullptr, 2560, Nn, rt, ct - 20, &sm);
    }
    gsync();

    // ---- superstep loop: chain level t  +  childsum level (maxd - t) ----
    for (int t = 0; t <= maxd; t++) {
        const int s_ch = g_lvlstart[t];
        const int n_ch = g_lvlstart[t + 1] - s_ch;
        const int d = maxd - t;
        const int s_cs = g_lvlstart[d];
        const int n_cs = g_lvlstart[d + 1] - s_cs;
        const int rt_ch = (n_ch + 63) >> 6;
        const int rt_cs = (n_cs + 63) >> 6;

        // stage1: chain g = h_par @ Wh^T (2048); childsum io (1024) + w (512)
        {
            const int t_ch = rt_ch * 16, t_cs = rt_cs * 12;
            for (int i = bid; i < t_ch + t_cs; i += nb) {
                if (i < t_ch) {
                    gemm_tf32(g_chh, g_parorder + s_ch, T_CHWH, chbh, g_chg,
                              g_order + s_ch, 2048, n_ch, i >> 4, i & 15, &sm);
                } else {
                    int j = i - t_ch, rt = j / 12, ct = j % 12;
                    if (ct < 8)
                        gemm_tf32(g_acch, g_order + s_cs, T_CSWIO, csbio, g_csio,
                                  g_order + s_cs, 1024, n_cs, rt, ct, &sm);
                    else
                        gemm_tf32(g_acczc, g_order + s_cs, T_CSWUM, csbum, g_csw,
                                  g_order + s_cs, 512, n_cs, rt, ct - 8, &sm);
                }
            }
        }
        gsync();

        // e1
        {
            const int total = (n_ch + n_cs) * Mm;
            for (int e = gidx; e < total; e += gstride) {
                if (e < n_ch * Mm) {
                    int r = e >> 9, j = e & 511;
                    int node = g_order[s_ch + r];
                    int p = g_parent[node];
                    const float* q = g_qx + (size_t)node * 2560;
                    const float* g = g_chg + (size_t)node * 2048;
                    float ig = sigf(q[j] + g[j]);
                    float og = sigf(q[512 + j] + g[512 + j]);
                    float fg = sigf(q[1024 + j] + g[1024 + j]);
                    float zg = sigf(q[1536 + j] + g[1536 + j]);
                    float pc = g_chc[(size_t)p * Mm + j];
                    size_t nj = (size_t)node * Mm + j;
                    g_chs[nj] = zg * tanhf(pc);
                    g_chig[nj] = ig; g_chog[nj] = og; g_chfc[nj] = fg * pc;
                } else {
                    int k = e - n_ch * Mm;
                    int r = k >> 9, j = k & 511;
                    int node = g_order[s_cs + r];
                    const float* px = g_px + (size_t)node * 2560;
                    const float* io = g_csio + (size_t)node * 1024;
                    size_t nj = (size_t)node * Mm + j;
                    float ig = sigf(px[j] + io[j]);
                    float og = sigf(px[1024 + j] + io[512 + j]);
                    float u = tanhf(px[2048 + j] + g_csw[nj]);
                    float c = ig * u + g_accfc[nj];
                    float h = og * tanhf(c);
                    g_csc[nj] = c; g_csh[nj] = h;
                }
            }
        }
        gsync();

        // stage2: chain w = s @ Wum^T (512); childsum fz = h @ Wfz^T (1024)
        {
            const int u_ch = rt_ch * 4, u_cs = rt_cs * 8;
            for (int i = bid; i < u_ch + u_cs; i += nb) {
                if (i < u_ch)
                    gemm_tf32(g_chs, g_order + s_ch, T_CHWUM, chbum, g_chw,
                              g_order + s_ch, 512, n_ch, i >> 2, i & 3, &sm);
                else {
                    int j = i - u_ch;
                    gemm_tf32(g_csh, g_order + s_cs, T_CSWFZ, csbfz, g_csfz,
                              g_order + s_cs, 1024, n_cs, j >> 3, j & 7, &sm);
                }
            }
        }
        gsync();

        // e2
        {
            const int total = (n_ch + n_cs) * Mm;
            for (int e = gidx; e < total; e += gstride) {
                if (e < n_ch * Mm) {
                    int r = e >> 9, j = e & 511;
                    int node = g_order[s_ch + r];
                    size_t nj = (size_t)node * Mm + j;
                    float u = tanhf(g_qx[(size_t)node * 2560 + 2048 + j] + g_chw[nj]);
                    float c = g_chig[nj] * u + g_chfc[nj];
                    float h = g_chog[nj] * tanhf(c);
                    g_chc[nj] = c; g_chh[nj] = h;
                } else {
                    int k = e - n_ch * Mm;
                    int r = k >> 9, j = k & 511;
                    int node = g_order[s_cs + r];
                    int p = g_parent[node];
                    size_t nj = (size_t)node * Mm + j;
                    const float* fz = g_csfz + (size_t)node * 1024;
                    float c = g_csc[nj], h = g_csh[nj];
                    float f = sigf(g_px[(size_t)p * 2560 + 512 + j] + fz[j]);
                    float z = sigf(g_px[(size_t)p * 2560 + 1536 + j] + fz[512 + j]);
                    size_t pj = (size_t)p * Mm + j;
                    atomicAdd(&g_acch[pj], h);
                    atomicAdd(&g_accfc[pj], f * c);
                    atomicAdd(&g_acczc[pj], z * tanhf(c));
                }
            }
        }
        gsync();
    }

    // ---- final: frep = h_root (node 0), brep = colmax(chain h) ----
    if (bid < 32) {
        float m0 = -1e30f, m1 = -1e30f;
        const int r0 = bid * 256, r1 = r0 + 256;
        for (int r = r0; r < r1; r++) {
            m0 = fmaxf(m0, g_chh[(size_t)r * Mm + tid]);
            m1 = fmaxf(m1, g_chh[(size_t)r * Mm + 256 + tid]);
        }
        atomicMaxF(out + 512 + tid, m0);
        atomicMaxF(out + 768 + tid, m1);
    } else if (bid == 32) {
        out[tid] = g_csh[tid];
        out[256 + tid] = g_csh[256 + tid];
    }
}

// ---------------- launch ----------------
extern "C" void kernel_launch(void* const* d_in, const int* in_sizes, int n_in,
                              void* d_out, int out_size) {
    const float* inputs = (const float*)d_in[0];
    const void* parent = d_in[1];
    const float* csWx = (const float*)d_in[2];
    const float* csbx = (const float*)d_in[3];
    const float* csWio = (const float*)d_in[4];
    const float* csbio = (const float*)d_in[5];
    const float* csWfz = (const float*)d_in[6];
    const float* csbfz = (const float*)d_in[7];
    const float* csWum = (const float*)d_in[8];
    const float* csbum = (const float*)d_in[9];
    const float* chWx = (const float*)d_in[10];
    const float* chbx = (const float*)d_in[11];
    const float* chWh = (const float*)d_in[12];
    const float* chbh = (const float*)d_in[13];
    const float* chWum = (const float*)d_in[14];
    const float* chbum = (const float*)d_in[15];
    float* out = (float*)d_out;

    // co-residency guarantee for the grid barrier (pure query; no allocation)
    int occ = 1;
    cudaOccupancyMaxActiveBlocksPerMultiprocessor(&occ, k_mega, 256, 0);
    if (occ < 1) occ = 1;
    int smcount = 148;
    cudaDeviceGetAttribute(&smcount, cudaDevAttrMultiProcessorCount, 0);
    int nb = smcount * (occ < 2 ? occ : 2);
    if (nb < 33) nb = 33;   // final phase needs 33 blocks

    k_decode<<<1, 1024>>>(parent);
    k_depth<<<64, 256>>>();
    k_levels<<<1, 1024>>>();
    k_mega<<<nb, 256>>>(inputs, csWx, csbx, csWio, csbio, csWfz, csbfz,
                        csWum, csbum, chWx, chbx, chWh, chbh, chWum, chbum, out);
}